// round 15
// baseline (speedup 1.0000x reference)
#include <cuda_runtime.h>
#include <cuda_fp16.h>
#include <cstdint>

#define NDIM   512
#define BK     32
#define NCH    (NDIM / BK)          // 16
#define CTA_M  128
#define CTA_N  128
#define NTHREADS 512
#define ROWB   80                   // padded row stride (32 fp16 = 64B + 16B pad)
#define TILEB  (128 * ROWB)         // 10240 B
#define STAGE_BYTES (2 * TILEB)     // A + B = 20480
#define NSTAGE 4
#define SMEM_STAGES (NSTAGE * STAGE_BYTES)    // 81920
#define MB_OFF      SMEM_STAGES               // 4 mbarriers (8B each)
#define FIX_OFF     (SMEM_STAGES + 64)
#define FIXLIST_OFF (SMEM_STAGES + 80)
#define CTA_FIXCAP  1024
#define SMEM_TOTAL  (FIXLIST_OFF + CTA_FIXCAP * 4)
#define THRESH 1e-3f
#define MMAX   32768

// ---- device scratch ----
__device__ float g_WT [NDIM * NDIM];                        // W^T fp32 (fixup)
__device__ __align__(256) char g_Xp[(size_t)NCH * MMAX * ROWB];  // chunk-major padded X fp16
__device__ __align__(256) char g_Wp[(size_t)NCH * NDIM * ROWB];  // chunk-major padded W^T fp16

__device__ __forceinline__ uint32_t smem_u32(const void* p) {
    uint32_t a;
    asm("{ .reg .u64 t; cvta.to.shared.u64 t, %1; cvt.u32.u64 %0, t; }" : "=r"(a) : "l"(p));
    return a;
}
__device__ __forceinline__ void mma_fp16(float* c, const uint32_t* a,
                                         uint32_t b0, uint32_t b1) {
    asm volatile(
        "mma.sync.aligned.m16n8k16.row.col.f32.f16.f16.f32 "
        "{%0,%1,%2,%3}, {%4,%5,%6,%7}, {%8,%9}, {%0,%1,%2,%3};\n"
        : "+f"(c[0]), "+f"(c[1]), "+f"(c[2]), "+f"(c[3])
        : "r"(a[0]), "r"(a[1]), "r"(a[2]), "r"(a[3]), "r"(b0), "r"(b1));
}
__device__ __forceinline__ void ldmx4(uint32_t* r, uint32_t addr) {
    asm volatile("ldmatrix.sync.aligned.m8n8.x4.shared.b16 {%0,%1,%2,%3}, [%4];"
        : "=r"(r[0]), "=r"(r[1]), "=r"(r[2]), "=r"(r[3]) : "r"(addr));
}
#define MBAR_INIT(a, c) asm volatile("mbarrier.init.shared.b64 [%0], %1;" :: "r"(a), "r"((uint32_t)(c)) : "memory")
#define MBAR_EXPECT_TX(a, b) asm volatile("mbarrier.arrive.expect_tx.shared.b64 _, [%0], %1;" :: "r"(a), "r"((uint32_t)(b)) : "memory")
#define MBAR_WAIT(a, ph) do { \
    uint32_t _m = (a), _p = (ph), _d; \
    asm volatile("{ .reg .pred p; mbarrier.try_wait.parity.shared.b64 p, [%1], %2; selp.b32 %0,1,0,p; }" \
        : "=r"(_d) : "r"(_m), "r"(_p) : "memory"); \
    if (!_d) { asm volatile( \
        "{ .reg .pred P1;\nWL_%=:\n mbarrier.try_wait.parity.shared.b64 P1, [%0], %1;\n @P1 bra.uni WD_%=;\n bra.uni WL_%=;\nWD_%=:\n }" \
        :: "r"(_m), "r"(_p) : "memory"); } \
} while (0)
#define BULK(dst, src, sz, mb) \
    asm volatile("cp.async.bulk.shared::cluster.global.mbarrier::complete_tx::bytes [%0], [%1], %2, [%3];" \
        :: "r"(dst), "l"(src), "r"((uint32_t)(sz)), "r"(mb) : "memory")

__device__ __forceinline__ uint32_t u32of(__half2 h) {
    return *reinterpret_cast<uint32_t*>(&h);
}

// ============================ prep ============================
// transpose + diag-zero: g_WT fp32 and g_Wp (chunk-major padded fp16)
__global__ void prep_w(const float* __restrict__ W) {
    __shared__ float tile[32][33];
    const int k0 = blockIdx.x * 32, n0 = blockIdx.y * 32;
    const int tx = threadIdx.x, ty = threadIdx.y;
    #pragma unroll
    for (int j = 0; j < 32; j += 8) {
        const int k = k0 + ty + j, n = n0 + tx;
        tile[ty + j][tx] = (k == n) ? 0.0f : W[k * NDIM + n];
    }
    __syncthreads();
    #pragma unroll
    for (int j = 0; j < 32; j += 8) {
        const int n = n0 + ty + j, k = k0 + tx;
        const float w = tile[tx][ty + j];
        g_WT[n * NDIM + k] = w;
        *reinterpret_cast<__half*>(
            g_Wp + ((size_t)(k >> 5) * NDIM + n) * ROWB + (k & 31) * 2) =
            __float2half_rn(w);
    }
}

// one thread handles one (m, chunk) row-piece: reads 128B fp32, writes 64B fp16
__global__ void prep_x(const float* __restrict__ X, int total) {
    int idx = blockIdx.x * blockDim.x + threadIdx.x;
    if (idx >= total) return;
    const int c = idx & 15;
    const int m = idx >> 4;
    const float4* src = reinterpret_cast<const float4*>(X + (size_t)m * NDIM + c * BK);
    char* dst = g_Xp + ((size_t)c * MMAX + m) * ROWB;
    #pragma unroll
    for (int j = 0; j < 4; ++j) {
        const float4 a = src[2 * j], b = src[2 * j + 1];
        *reinterpret_cast<uint4*>(dst + j * 16) = make_uint4(
            u32of(__floats2half2_rn(a.x, a.y)), u32of(__floats2half2_rn(a.z, a.w)),
            u32of(__floats2half2_rn(b.x, b.y)), u32of(__floats2half2_rn(b.z, b.w)));
    }
}

// ============================ main (GEMM + gate + in-CTA fixup) ============================
__global__ __launch_bounds__(NTHREADS, 2)
void li_mma_kernel(const float* __restrict__ X,
                   const float* __restrict__ bias,
                   float* __restrict__ out)
{
    extern __shared__ char smem[];
    const uint32_t sb = smem_u32(smem);
    const int tid = threadIdx.x;
    const int lid = tid & 31;
    const int wid = tid >> 5;          // 0..15
    const int wm  = wid >> 2;          // 0..3 -> m offset 32
    const int wn  = wid & 3;           // 0..3 -> n offset 32
    const int g   = lid >> 2;          // 0..7
    const int t   = lid & 3;           // 0..3
    const int q   = lid >> 3;          // 0..3
    const int rl  = lid & 7;           // 0..7
    const int cta_n = blockIdx.x * CTA_N;
    const size_t cta_m = (size_t)blockIdx.y * CTA_M;

    unsigned int* fixcnt  = reinterpret_cast<unsigned int*>(smem + FIX_OFF);
    unsigned int* fixlist = reinterpret_cast<unsigned int*>(smem + FIXLIST_OFF);
    if (tid == 0) {
        *fixcnt = 0;
        #pragma unroll
        for (int s = 0; s < NSTAGE; ++s) MBAR_INIT(sb + MB_OFF + s * 8, 1);
    }
    __syncthreads();

    float acc[2][4][4];
    #pragma unroll
    for (int a = 0; a < 2; ++a)
        #pragma unroll
        for (int b = 0; b < 4; ++b)
            #pragma unroll
            for (int c = 0; c < 4; ++c) acc[a][b][c] = 0.0f;

    auto issueLoad = [&](int chunk) {
        const int s = chunk & (NSTAGE - 1);
        const uint32_t st = sb + (uint32_t)s * STAGE_BYTES;
        const uint32_t mb = sb + MB_OFF + s * 8;
        MBAR_EXPECT_TX(mb, STAGE_BYTES);
        BULK(st,         g_Xp + ((size_t)chunk * MMAX + cta_m) * ROWB, TILEB, mb);
        BULK(st + TILEB, g_Wp + ((size_t)chunk * NDIM + cta_n) * ROWB, TILEB, mb);
    };

    auto compute = [&](int chunk) {
        const uint32_t st = sb + (uint32_t)(chunk & (NSTAGE - 1)) * STAGE_BYTES;
        #pragma unroll
        for (int ks = 0; ks < 2; ++ks) {
            uint32_t bh[4][2];
            #pragma unroll
            for (int ntp = 0; ntp < 2; ++ntp) {
                uint32_t baddr = st + TILEB
                    + (uint32_t)(wn * 32 + (ntp * 2 + (q >> 1)) * 8 + rl) * ROWB
                    + ks * 32 + (q & 1) * 16;
                uint32_t rr[4];
                ldmx4(rr, baddr);
                bh[2 * ntp][0] = rr[0]; bh[2 * ntp][1] = rr[1];
                bh[2 * ntp + 1][0] = rr[2]; bh[2 * ntp + 1][1] = rr[3];
            }
            #pragma unroll
            for (int mt = 0; mt < 2; ++mt) {
                uint32_t aaddr = st
                    + (uint32_t)(wm * 32 + mt * 16 + (q & 1) * 8 + rl) * ROWB
                    + ks * 32 + (q >> 1) * 16;
                uint32_t Ah[4];
                ldmx4(Ah, aaddr);
                #pragma unroll
                for (int nt = 0; nt < 4; ++nt)
                    mma_fp16(acc[mt][nt], Ah, bh[nt][0], bh[nt][1]);
            }
        }
    };

    // ---- 4-stage mbarrier pipeline ----
    if (tid == 0) { issueLoad(0); issueLoad(1); issueLoad(2); }
    for (int i = 0; i < NCH; ++i) {
        __syncthreads();   // all warps done with compute(i-1) -> stage (i+3)&3 free
        if (tid == 0 && i + 3 < NCH) issueLoad(i + 3);
        MBAR_WAIT(sb + MB_OFF + (i & 3) * 8, (i >> 2) & 1);
        compute(i);
    }

    // ---- epilogue: bias + gate; flag tiny |inhib| into CTA-local worklist ----
    #pragma unroll
    for (int mt = 0; mt < 2; ++mt) {
        #pragma unroll
        for (int nt = 0; nt < 4; ++nt) {
            const int gcol = cta_n + wn * 32 + nt * 8 + 2 * t;
            const float b0 = bias[gcol], b1 = bias[gcol + 1];
            #pragma unroll
            for (int half = 0; half < 2; ++half) {
                const size_t grow = cta_m + wm * 32 + mt * 16 + g + half * 8;
                const float v0 = acc[mt][nt][half * 2 + 0] + b0;
                const float v1 = acc[mt][nt][half * 2 + 1] + b1;
                if (fabsf(v0) < THRESH) {
                    unsigned int s = atomicAdd(fixcnt, 1u);
                    if (s < CTA_FIXCAP) fixlist[s] = (unsigned int)(grow * NDIM + gcol);
                }
                if (fabsf(v1) < THRESH) {
                    unsigned int s = atomicAdd(fixcnt, 1u);
                    if (s < CTA_FIXCAP) fixlist[s] = (unsigned int)(grow * NDIM + gcol + 1);
                }
                const float2 xv = *reinterpret_cast<const float2*>(
                    X + grow * NDIM + gcol);
                float2 o;
                o.x = v0 > 0.0f ? xv.x : 0.0f;
                o.y = v1 > 0.0f ? xv.y : 0.0f;
                *reinterpret_cast<float2*>(out + grow * NDIM + gcol) = o;
            }
        }
    }

    // ---- in-CTA fixup: exact fp32 dot per flagged element (one warp each) ----
    __syncthreads();
    const unsigned int cnt = min(*fixcnt, (unsigned int)CTA_FIXCAP);
    for (unsigned int j = (unsigned int)wid; j < cnt; j += (NTHREADS / 32)) {
        const unsigned int e = fixlist[j];
        const unsigned int row = e >> 9;
        const unsigned int col = e & (NDIM - 1);
        const float4* xr = reinterpret_cast<const float4*>(X + (size_t)row * NDIM);
        const float4* wr = reinterpret_cast<const float4*>(g_WT + (size_t)col * NDIM);
        float s = 0.0f;
        #pragma unroll
        for (int k = 0; k < NDIM / 128; ++k) {
            const float4 xv = xr[k * 32 + lid];
            const float4 wv = wr[k * 32 + lid];
            s = fmaf(xv.x, wv.x, s);
            s = fmaf(xv.y, wv.y, s);
            s = fmaf(xv.z, wv.z, s);
            s = fmaf(xv.w, wv.w, s);
        }
        #pragma unroll
        for (int off = 16; off > 0; off >>= 1)
            s += __shfl_xor_sync(0xFFFFFFFF, s, off);
        if (lid == 0) {
            const float v = s + bias[col];
            out[(size_t)e] = v > 0.0f ? X[(size_t)row * NDIM + col] : 0.0f;
        }
    }
}

// ============================ host ============================
extern "C" void kernel_launch(void* const* d_in, const int* in_sizes, int n_in,
                              void* d_out, int out_size)
{
    const float* X    = (const float*)d_in[0];
    const float* W    = (const float*)d_in[1];
    const float* bias = (const float*)d_in[2];
    float* out = (float*)d_out;
    const int M = in_sizes[0] / NDIM;   // 32768

    dim3 pgrid(NDIM / 32, NDIM / 32);
    prep_w<<<pgrid, dim3(32, 8)>>>(W);
    const int total = M * NCH;
    prep_x<<<(total + 255) / 256, 256>>>(X, total);

    cudaFuncSetAttribute(li_mma_kernel,
                         cudaFuncAttributeMaxDynamicSharedMemorySize, SMEM_TOTAL);
    dim3 grid(NDIM / CTA_N, M / CTA_M);   // (4, 256)
    li_mma_kernel<<<grid, NTHREADS, SMEM_TOTAL>>>(X, bias, out);
}

// round 16
// speedup vs baseline: 1.1035x; 1.1035x over previous
#include <cuda_runtime.h>
#include <cuda_fp16.h>
#include <cstdint>

#define NDIM   512
#define BK     32
#define NCH    (NDIM / BK)          // 16
#define CTA_M  128
#define CTA_N  128
#define NTHREADS 512
#define ROWB   80                   // padded smem row stride (32 fp16 = 64B + 16B pad)
#define TILEB  (128 * ROWB)         // 10240 B
#define STAGE_BYTES (2 * TILEB)     // A + B = 20480
#define NSTAGE 4
#define SMEM_STAGES (NSTAGE * STAGE_BYTES)    // 81920
#define FIX_OFF     SMEM_STAGES               // u32 counter
#define FIXLIST_OFF (SMEM_STAGES + 16)
#define CTA_FIXCAP  1024
#define SMEM_TOTAL  (FIXLIST_OFF + CTA_FIXCAP * 4)
#define THRESH 1e-3f
#define MMAX   32768

// ---- device scratch ----
__device__ float  g_WT [NDIM * NDIM];            // W^T (n,k), diag=0, fp32 (fixup)
__device__ __half g_Whf[NDIM * NDIM];            // W^T fp16
__device__ __half g_Xh [(size_t)MMAX * NDIM];    // X fp16

__device__ __forceinline__ uint32_t smem_u32(const void* p) {
    uint32_t a;
    asm("{ .reg .u64 t; cvta.to.shared.u64 t, %1; cvt.u32.u64 %0, t; }" : "=r"(a) : "l"(p));
    return a;
}
__device__ __forceinline__ void mma_fp16(float* c, const uint32_t* a,
                                         uint32_t b0, uint32_t b1) {
    asm volatile(
        "mma.sync.aligned.m16n8k16.row.col.f32.f16.f16.f32 "
        "{%0,%1,%2,%3}, {%4,%5,%6,%7}, {%8,%9}, {%0,%1,%2,%3};\n"
        : "+f"(c[0]), "+f"(c[1]), "+f"(c[2]), "+f"(c[3])
        : "r"(a[0]), "r"(a[1]), "r"(a[2]), "r"(a[3]), "r"(b0), "r"(b1));
}
__device__ __forceinline__ void ldmx4(uint32_t* r, uint32_t addr) {
    asm volatile("ldmatrix.sync.aligned.m8n8.x4.shared.b16 {%0,%1,%2,%3}, [%4];"
        : "=r"(r[0]), "=r"(r[1]), "=r"(r[2]), "=r"(r[3]) : "r"(addr));
}
#define CP16(dst, src) \
    asm volatile("cp.async.cg.shared.global [%0], [%1], 16;\n" :: "r"(dst), "l"(src))
#define CP_COMMIT()  asm volatile("cp.async.commit_group;\n" ::: "memory")
#define CP_WAITG(n)  asm volatile("cp.async.wait_group %0;\n" :: "n"(n) : "memory")

__device__ __forceinline__ uint32_t u32of(__half2 h) {
    return *reinterpret_cast<uint32_t*>(&h);
}

// ============================ fused prep ============================
// blocks [0,256): W transpose tiles; blocks [256,...): X fp16 conversion.
// prep_w rides inside prep_x's bandwidth-bound wave.
__global__ void prep_all(const float* __restrict__ W,
                         const float* __restrict__ X, int total4) {
    if (blockIdx.x < 256) {
        __shared__ float tile[32][33];
        const int k0 = (blockIdx.x & 15) * 32, n0 = (blockIdx.x >> 4) * 32;
        const int tx = threadIdx.x & 31, ty = threadIdx.x >> 5;   // (32,8)
        #pragma unroll
        for (int j = 0; j < 32; j += 8) {
            const int k = k0 + ty + j, n = n0 + tx;
            tile[ty + j][tx] = (k == n) ? 0.0f : W[k * NDIM + n];
        }
        __syncthreads();
        #pragma unroll
        for (int j = 0; j < 32; j += 8) {
            const int n = n0 + ty + j, k = k0 + tx;
            const float w = tile[tx][ty + j];
            g_WT [n * NDIM + k] = w;
            g_Whf[n * NDIM + k] = __float2half_rn(w);
        }
    } else {
        const int idx = (blockIdx.x - 256) * blockDim.x + threadIdx.x;
        if (idx >= total4) return;
        float4 v = reinterpret_cast<const float4*>(X)[idx];
        __half2 h01 = __floats2half2_rn(v.x, v.y);
        __half2 h23 = __floats2half2_rn(v.z, v.w);
        reinterpret_cast<uint2*>(g_Xh)[idx] = make_uint2(u32of(h01), u32of(h23));
    }
}

// ============================ main (GEMM + gate + in-CTA fixup) ============================
__global__ __launch_bounds__(NTHREADS, 2)
void li_mma_kernel(const float* __restrict__ X,
                   const float* __restrict__ bias,
                   float* __restrict__ out)
{
    extern __shared__ char smem[];
    const uint32_t sb = smem_u32(smem);
    const int tid = threadIdx.x;
    const int lid = tid & 31;
    const int wid = tid >> 5;          // 0..15
    const int wm  = wid >> 2;          // 0..3 -> m offset 32
    const int wn  = wid & 3;           // 0..3 -> n offset 32
    const int g   = lid >> 2;          // 0..7
    const int t   = lid & 3;           // 0..3
    const int q   = lid >> 3;          // 0..3
    const int rl  = lid & 7;           // 0..7
    const int cta_n = blockIdx.x * CTA_N;
    const size_t cta_m = (size_t)blockIdx.y * CTA_M;

    unsigned int* fixcnt  = reinterpret_cast<unsigned int*>(smem + FIX_OFF);
    unsigned int* fixlist = reinterpret_cast<unsigned int*>(smem + FIXLIST_OFF);
    if (tid == 0) *fixcnt = 0;

    float acc[2][4][4];
    #pragma unroll
    for (int a = 0; a < 2; ++a)
        #pragma unroll
        for (int b = 0; b < 4; ++b)
            #pragma unroll
            for (int c = 0; c < 4; ++c) acc[a][b][c] = 0.0f;

    auto loadStage = [&](int chunk) {
        const uint32_t st = sb + (uint32_t)(chunk & (NSTAGE - 1)) * STAGE_BYTES;
        const char* xh = (const char*)g_Xh;
        const char* wh = (const char*)g_Whf;
        int row = tid >> 2, c4 = tid & 3;
        uint32_t doff = row * ROWB + c4 * 16;
        size_t gA = ((cta_m + row) * NDIM + (size_t)chunk * BK) * 2 + c4 * 16;
        size_t gB = (((size_t)cta_n + row) * NDIM + (size_t)chunk * BK) * 2 + c4 * 16;
        CP16(st + doff,         xh + gA);
        CP16(st + TILEB + doff, wh + gB);
        CP_COMMIT();
    };

    auto compute = [&](int chunk) {
        const uint32_t st = sb + (uint32_t)(chunk & (NSTAGE - 1)) * STAGE_BYTES;
        #pragma unroll
        for (int ks = 0; ks < 2; ++ks) {
            uint32_t bh[4][2];
            #pragma unroll
            for (int ntp = 0; ntp < 2; ++ntp) {
                uint32_t baddr = st + TILEB
                    + (uint32_t)(wn * 32 + (ntp * 2 + (q >> 1)) * 8 + rl) * ROWB
                    + ks * 32 + (q & 1) * 16;
                uint32_t rr[4];
                ldmx4(rr, baddr);
                bh[2 * ntp][0] = rr[0]; bh[2 * ntp][1] = rr[1];
                bh[2 * ntp + 1][0] = rr[2]; bh[2 * ntp + 1][1] = rr[3];
            }
            #pragma unroll
            for (int mt = 0; mt < 2; ++mt) {
                uint32_t aaddr = st
                    + (uint32_t)(wm * 32 + mt * 16 + (q & 1) * 8 + rl) * ROWB
                    + ks * 32 + (q >> 1) * 16;
                uint32_t Ah[4];
                ldmx4(Ah, aaddr);
                #pragma unroll
                for (int nt = 0; nt < 4; ++nt)
                    mma_fp16(acc[mt][nt], Ah, bh[nt][0], bh[nt][1]);
            }
        }
    };

    // ---- 4-stage pipeline ----
    loadStage(0); loadStage(1); loadStage(2);
    for (int i = 0; i < NCH; ++i) {
        if (i + 3 < NCH) { CP_WAITG(2); } else { CP_WAITG(0); }
        __syncthreads();
        compute(i);
        if (i + 3 < NCH) loadStage(i + 3);
    }

    // ---- epilogue: bias + gate; flag tiny |inhib| into CTA-local worklist ----
    #pragma unroll
    for (int mt = 0; mt < 2; ++mt) {
        #pragma unroll
        for (int nt = 0; nt < 4; ++nt) {
            const int gcol = cta_n + wn * 32 + nt * 8 + 2 * t;
            const float b0 = bias[gcol], b1 = bias[gcol + 1];
            #pragma unroll
            for (int half = 0; half < 2; ++half) {
                const size_t grow = cta_m + wm * 32 + mt * 16 + g + half * 8;
                const float v0 = acc[mt][nt][half * 2 + 0] + b0;
                const float v1 = acc[mt][nt][half * 2 + 1] + b1;
                if (fabsf(v0) < THRESH) {
                    unsigned int s = atomicAdd(fixcnt, 1u);
                    if (s < CTA_FIXCAP) fixlist[s] = (unsigned int)(grow * NDIM + gcol);
                }
                if (fabsf(v1) < THRESH) {
                    unsigned int s = atomicAdd(fixcnt, 1u);
                    if (s < CTA_FIXCAP) fixlist[s] = (unsigned int)(grow * NDIM + gcol + 1);
                }
                const float2 xv = *reinterpret_cast<const float2*>(
                    X + grow * NDIM + gcol);
                float2 o;
                o.x = v0 > 0.0f ? xv.x : 0.0f;
                o.y = v1 > 0.0f ? xv.y : 0.0f;
                *reinterpret_cast<float2*>(out + grow * NDIM + gcol) = o;
            }
        }
    }

    // ---- in-CTA fixup: exact fp32 dot per flagged element (one warp each) ----
    __syncthreads();
    const unsigned int cnt = min(*fixcnt, (unsigned int)CTA_FIXCAP);
    for (unsigned int j = (unsigned int)wid; j < cnt; j += (NTHREADS / 32)) {
        const unsigned int e = fixlist[j];
        const unsigned int row = e >> 9;
        const unsigned int col = e & (NDIM - 1);
        const float4* xr = reinterpret_cast<const float4*>(X + (size_t)row * NDIM);
        const float4* wr = reinterpret_cast<const float4*>(g_WT + (size_t)col * NDIM);
        float s = 0.0f;
        #pragma unroll
        for (int k = 0; k < NDIM / 128; ++k) {
            const float4 xv = xr[k * 32 + lid];
            const float4 wv = wr[k * 32 + lid];
            s = fmaf(xv.x, wv.x, s);
            s = fmaf(xv.y, wv.y, s);
            s = fmaf(xv.z, wv.z, s);
            s = fmaf(xv.w, wv.w, s);
        }
        #pragma unroll
        for (int off = 16; off > 0; off >>= 1)
            s += __shfl_xor_sync(0xFFFFFFFF, s, off);
        if (lid == 0) {
            const float v = s + bias[col];
            out[(size_t)e] = v > 0.0f ? X[(size_t)row * NDIM + col] : 0.0f;
        }
    }
}

// ============================ host ============================
extern "C" void kernel_launch(void* const* d_in, const int* in_sizes, int n_in,
                              void* d_out, int out_size)
{
    const float* X    = (const float*)d_in[0];
    const float* W    = (const float*)d_in[1];
    const float* bias = (const float*)d_in[2];
    float* out = (float*)d_out;
    const int M = in_sizes[0] / NDIM;   // 32768

    const int total4 = M * NDIM / 4;                 // 4,194,304
    const int xblocks = (total4 + 255) / 256;        // 16384
    prep_all<<<256 + xblocks, 256>>>(W, X, total4);

    cudaFuncSetAttribute(li_mma_kernel,
                         cudaFuncAttributeMaxDynamicSharedMemorySize, SMEM_TOTAL);
    dim3 grid(NDIM / CTA_N, M / CTA_M);   // (4, 256)
    li_mma_kernel<<<grid, NTHREADS, SMEM_TOTAL>>>(X, bias, out);
}